// round 15
// baseline (speedup 1.0000x reference)
#include <cuda_runtime.h>
#include <cuda_fp16.h>
#include <cstdint>

// Problem constants
#define BB   8
#define LL   4096
#define DD   768
#define NE   64
#define KC   4
#define PP   64
#define DIc  1536
#define HHc  24
#define CDc  1664
#define DIPc 3224
#define MROWS (BB*LL)   // 32768
#define NPAD1 3328
#define NCHUNK 64
#define DTOFF 3200      // = DIc + CDc

// ---------------- workspace ----------------
__device__ __half g_xnh[(size_t)MROWS*DD];
__device__ __half g_zxh[(size_t)MROWS*DIPc];          // GEMM1 out (fp16)
__device__ float  g_dtf[(size_t)MROWS*HHc];           // raw dt columns (fp32)
__device__ __half g_y[(size_t)MROWS*DIc];             // scan out (fp16)
__device__ __half g_gh[(size_t)MROWS*DIc];
__device__ __half g_w1h[(size_t)NPAD1*DD];
__device__ __half g_w2h[(size_t)DD*DIc];
__device__ __half g_Sh[(size_t)BB*HHc*NCHUNK*4096];   // chunk states -> H snapshots
__device__ __half g_Bc[(size_t)MROWS*NE];             // conv+silu B  [t][n]
__device__ __half g_Cc[(size_t)MROWS*NE];             // conv+silu C  [t][n]
__device__ __half g_BT[(size_t)BB*NE*LL];             // conv+silu B^T [b][n][t]
__device__ float  g_LP[(size_t)BB*HHc*NCHUNK*64];

// ---------------- helpers ----------------
__device__ __forceinline__ uint32_t smem_u32(const void* p) {
    uint32_t a;
    asm("{ .reg .u64 t; cvta.to.shared.u64 t, %1; cvt.u32.u64 %0, t; }" : "=r"(a) : "l"(p));
    return a;
}
__device__ __forceinline__ void cp16(uint32_t dst, const void* src) {
    asm volatile("cp.async.cg.shared.global [%0], [%1], 16;" :: "r"(dst), "l"(src));
}
#define CP_COMMIT() asm volatile("cp.async.commit_group;" ::: "memory")
#define CP_WAIT1()  asm volatile("cp.async.wait_group 1;" ::: "memory")
#define CP_WAIT0()  asm volatile("cp.async.wait_group 0;" ::: "memory")

__device__ __forceinline__ void ldsm4(uint32_t r[4], uint32_t addr) {
    asm volatile("ldmatrix.sync.aligned.m8n8.x4.shared.b16 {%0,%1,%2,%3}, [%4];"
        : "=r"(r[0]), "=r"(r[1]), "=r"(r[2]), "=r"(r[3]) : "r"(addr));
}

__device__ __forceinline__ void mma_f16(float c[4], const uint32_t a[4],
                                        uint32_t b0, uint32_t b1) {
    asm volatile(
        "mma.sync.aligned.m16n8k16.row.col.f32.f16.f16.f32 "
        "{%0,%1,%2,%3},{%4,%5,%6,%7},{%8,%9},{%0,%1,%2,%3};\n"
        : "+f"(c[0]), "+f"(c[1]), "+f"(c[2]), "+f"(c[3])
        : "r"(a[0]), "r"(a[1]), "r"(a[2]), "r"(a[3]), "r"(b0), "r"(b1));
}

__device__ __forceinline__ float fsilu(float a) {
    return __fdividef(a, 1.f + __expf(-a));
}

// swizzled byte offset within a 64-half (128B) row array
__device__ __forceinline__ int swzoff(int r, int col) {
    return r * 128 + ((((col >> 3) ^ (r & 7)) << 4)) + ((col & 7) << 1);
}
__device__ __forceinline__ uint32_t swzchunk(int r, int chunk) {
    return (uint32_t)(r * 128 + (((chunk ^ (r & 7)) << 4)));
}

// ---------------- fp16 GEMM (templated output type, optional dt capture) -----
static constexpr int GSTAGE = 32768;
static constexpr int GSMEM  = 3 * GSTAGE;

template <int KDIM, bool ADDRES, bool HALFOUT, bool DTW>
__global__ void __launch_bounds__(256, 2) gemm_h(const __half* __restrict__ A,
                                                 const __half* __restrict__ W,
                                                 const float* __restrict__ Res,
                                                 void* __restrict__ OutV, int Ntot) {
    extern __shared__ char smem[];
    uint32_t sbase = smem_u32(smem);
    constexpr int KT = KDIM / 64;

    int tid = threadIdx.x;
    int bm0 = blockIdx.y * 128, bn0 = blockIdx.x * 128;
    int warp = tid >> 5, lane = tid & 31;
    int wm = (warp & 1) * 64, wn = (warp >> 1) * 32;
    int g = lane >> 2, tg = lane & 3;

    float acc[4][4][4];
#pragma unroll
    for (int i = 0; i < 4; i++)
#pragma unroll
        for (int j = 0; j < 4; j++)
#pragma unroll
            for (int k = 0; k < 4; k++) acc[i][j][k] = 0.f;

    int srow = tid >> 1;
    int scb  = (tid & 1) * 4;
    int sswz = srow & 7;
    const __half* gA = A + (size_t)(bm0 + srow) * KDIM + scb * 8;
    const __half* gB = W + (size_t)(bn0 + srow) * KDIM + scb * 8;
    uint32_t stA = sbase + srow * 128;
    uint32_t stB = stA + 16384;

#define LOAD_STAGE(s, t) do { \
        uint32_t so = (uint32_t)(s) * GSTAGE; \
        const __half* a = gA + (t) * 64; \
        const __half* b = gB + (t) * 64; \
        _Pragma("unroll") \
        for (int i = 0; i < 4; i++) { \
            uint32_t off = (uint32_t)(((scb + i) ^ sswz) * 16); \
            cp16(stA + so + off, a + i * 8); \
            cp16(stB + so + off, b + i * 8); \
        } \
    } while (0)

    LOAD_STAGE(0, 0); CP_COMMIT();
    LOAD_STAGE(1, 1); CP_COMMIT();

    int arow = wm + (lane & 15);
    int aks  = lane >> 4;
    int aswz = arow & 7;
    int brow = wn + ((lane >> 4) << 3) + (lane & 7);
    int bks  = (lane >> 3) & 1;
    int bswz = brow & 7;

    for (int t = 0; t < KT; t++) {
        CP_WAIT1();
        __syncthreads();
        if (t + 2 < KT) { LOAD_STAGE((t + 2) % 3, t + 2); CP_COMMIT(); }

        uint32_t Abase = sbase + (uint32_t)(t % 3) * GSTAGE;
        uint32_t Bbase = Abase + 16384;
#pragma unroll
        for (int ks = 0; ks < 4; ks++) {
            uint32_t a[4][4], bb[2][4];
#pragma unroll
            for (int mt = 0; mt < 4; mt++)
                ldsm4(a[mt], Abase + (arow + mt * 16) * 128 +
                              (uint32_t)(((ks * 2 + aks) ^ aswz) * 16));
#pragma unroll
            for (int np = 0; np < 2; np++)
                ldsm4(bb[np], Bbase + (brow + np * 16) * 128 +
                               (uint32_t)(((ks * 2 + bks) ^ bswz) * 16));
#pragma unroll
            for (int mt = 0; mt < 4; mt++)
#pragma unroll
                for (int nt = 0; nt < 4; nt++)
                    mma_f16(acc[mt][nt], a[mt],
                            bb[nt >> 1][(nt & 1) * 2], bb[nt >> 1][(nt & 1) * 2 + 1]);
        }
    }
#undef LOAD_STAGE

#pragma unroll
    for (int mt = 0; mt < 4; mt++) {
        int r0 = bm0 + wm + mt * 16 + g;
#pragma unroll
        for (int nt = 0; nt < 4; nt++) {
            int c0 = bn0 + wn + nt * 8 + tg * 2;
            if (c0 < Ntot) {
                float2 v0 = make_float2(acc[mt][nt][0], acc[mt][nt][1]);
                float2 v1 = make_float2(acc[mt][nt][2], acc[mt][nt][3]);
                if (ADDRES) {
                    float2 x0 = *(const float2*)(Res + (size_t)r0 * Ntot + c0);
                    float2 x1 = *(const float2*)(Res + (size_t)(r0 + 8) * Ntot + c0);
                    v0.x += x0.x; v0.y += x0.y;
                    v1.x += x1.x; v1.y += x1.y;
                }
                if (DTW) {
                    if (c0 >= DTOFF && c0 < DTOFF + HHc) {
                        int dc = c0 - DTOFF;
                        g_dtf[(size_t)r0 * HHc + dc]       = v0.x;
                        g_dtf[(size_t)r0 * HHc + dc + 1]   = v0.y;
                        g_dtf[(size_t)(r0 + 8) * HHc + dc]     = v1.x;
                        g_dtf[(size_t)(r0 + 8) * HHc + dc + 1] = v1.y;
                    }
                }
                if (HALFOUT) {
                    __half* Out = (__half*)OutV;
                    *(__half2*)(Out + (size_t)r0 * Ntot + c0) = __floats2half2_rn(v0.x, v0.y);
                    *(__half2*)(Out + (size_t)(r0 + 8) * Ntot + c0) = __floats2half2_rn(v1.x, v1.y);
                } else {
                    float* Out = (float*)OutV;
                    *(float2*)(Out + (size_t)r0 * Ntot + c0) = v0;
                    *(float2*)(Out + (size_t)(r0 + 8) * Ntot + c0) = v1;
                }
            }
        }
    }
}

// ---------------- LayerNorm (vectorized float4 in, half2 out) ----------------
__global__ void ln_kernel(const float* __restrict__ x,
                          const float* __restrict__ w,
                          const float* __restrict__ b) {
    int row = blockIdx.x;
    int tid = threadIdx.x;
    const float* xr = x + (size_t)row * DD;
    float4 v4 = make_float4(0.f, 0.f, 0.f, 0.f);
    float s = 0.f, s2 = 0.f;
    if (tid < 192) {
        v4 = *(const float4*)(xr + tid * 4);
        s  = v4.x + v4.y + v4.z + v4.w;
        s2 = v4.x * v4.x + v4.y * v4.y + v4.z * v4.z + v4.w * v4.w;
    }
    __shared__ float red0[8], red1[8];
    for (int o = 16; o; o >>= 1) {
        s  += __shfl_xor_sync(0xffffffffu, s,  o);
        s2 += __shfl_xor_sync(0xffffffffu, s2, o);
    }
    int warp = tid >> 5, lane = tid & 31;
    if (lane == 0) { red0[warp] = s; red1[warp] = s2; }
    __syncthreads();
    if (warp == 0) {
        s  = (lane < 8) ? red0[lane] : 0.f;
        s2 = (lane < 8) ? red1[lane] : 0.f;
        for (int o = 4; o; o >>= 1) {
            s  += __shfl_xor_sync(0xffffffffu, s,  o);
            s2 += __shfl_xor_sync(0xffffffffu, s2, o);
        }
        if (lane == 0) { red0[0] = s; red1[0] = s2; }
    }
    __syncthreads();
    float mu  = red0[0] * (1.f / DD);
    float var = red1[0] * (1.f / DD) - mu * mu;
    float rs  = rsqrtf(var + 1e-5f);
    if (tid < 192) {
        float4 w4 = *(const float4*)(w + tid * 4);
        float4 b4 = *(const float4*)(b + tid * 4);
        __half2* o = (__half2*)(g_xnh + (size_t)row * DD + tid * 4);
        o[0] = __floats2half2_rn((v4.x - mu) * rs * w4.x + b4.x,
                                 (v4.y - mu) * rs * w4.y + b4.y);
        o[1] = __floats2half2_rn((v4.z - mu) * rs * w4.z + b4.z,
                                 (v4.w - mu) * rs * w4.w + b4.w);
    }
}

// ---------------- weight converts ----------------
__global__ void cvtW1_kernel(const float* __restrict__ W1) {
    int idx = blockIdx.x * 256 + threadIdx.x;
    if (idx >= NPAD1 * DD) return;
    int r = idx / DD;
    g_w1h[idx] = (r < DIPc) ? __float2half(W1[idx]) : __half(0.f);
}
__global__ void cvtW2_kernel(const float* __restrict__ W2) {
    int idx = blockIdx.x * 256 + threadIdx.x;
    if (idx >= DD * DIc) return;
    g_w2h[idx] = __float2half(W2[idx]);
}

// ---------------- pre: conv+silu for B/C channels (h-independent, once) -------
__global__ void __launch_bounds__(256) pre_kernel(const float* __restrict__ cw,
                                                  const float* __restrict__ cb) {
    __shared__ __half sTmp[64][72];
    int blk = blockIdx.x;
    int gl0 = blk * 64;
    int b = gl0 / LL;
    int l0 = gl0 % LL;
    int tid = threadIdx.x;
    int j = tid & 63, seg = tid >> 6;
    const __half* z0 = g_zxh + (size_t)b * LL * DIPc;
    int cBi = DIc + j, cCi = DIc + NE + j;
    float wB0 = cw[cBi*4], wB1 = cw[cBi*4+1], wB2 = cw[cBi*4+2], wB3 = cw[cBi*4+3];
    float wC0 = cw[cCi*4], wC1 = cw[cCi*4+1], wC2 = cw[cCi*4+2], wC3 = cw[cCi*4+3];
    float bBv = cb[cBi], bCv = cb[cCi];
    const __half* pB = z0 + 2 * DIc + j;
    const __half* pC = z0 + 2 * DIc + NE + j;

    int t0 = seg * 16;
    int lb = l0 + t0;
    float B0 = 0.f, B1 = 0.f, B2 = 0.f, C0 = 0.f, C1 = 0.f, C2 = 0.f;
    if (lb - 3 >= 0) { size_t o = (size_t)(lb-3)*DIPc; B0 = __half2float(pB[o]); C0 = __half2float(pC[o]); }
    if (lb - 2 >= 0) { size_t o = (size_t)(lb-2)*DIPc; B1 = __half2float(pB[o]); C1 = __half2float(pC[o]); }
    if (lb - 1 >= 0) { size_t o = (size_t)(lb-1)*DIPc; B2 = __half2float(pB[o]); C2 = __half2float(pC[o]); }
#pragma unroll
    for (int it = 0; it < 16; it++) {
        int t = t0 + it;
        size_t o = (size_t)(lb + it) * DIPc;
        float B3 = __half2float(pB[o]), C3 = __half2float(pC[o]);
        float aB = bBv + wB0*B0 + wB1*B1 + wB2*B2 + wB3*B3;
        float aC = bCv + wC0*C0 + wC1*C1 + wC2*C2 + wC3*C3;
        float Bs = fsilu(aB);
        float Cs = fsilu(aC);
        __half Bh = __float2half(Bs);
        g_Bc[((size_t)(gl0 + t) << 6) + j] = Bh;
        g_Cc[((size_t)(gl0 + t) << 6) + j] = __float2half(Cs);
        sTmp[t][j] = Bh;
        B0 = B1; B1 = B2; B2 = B3;
        C0 = C1; C1 = C2; C2 = C3;
    }
    __syncthreads();
    int n = tid >> 2, tq = tid & 3;
    __half* dst = g_BT + ((size_t)(b * NE + n) * LL + l0 + tq * 16);
#pragma unroll
    for (int i = 0; i < 8; i++) {
        int t = tq * 16 + i * 2;
        *(__half2*)(dst + i * 2) = __halves2half2(sTmp[t][n], sTmp[t + 1][n]);
    }
}

// ================= chunked SSD scan, tensor-core + cp.async staging ==========
__global__ void __launch_bounds__(256, 4) chunk_kernel(const float* __restrict__ D_skip,
                                                       const float* __restrict__ dt_bias,
                                                       const float* __restrict__ A_log,
                                                       const float* __restrict__ cw,
                                                       const float* __restrict__ cb) {
    int c = blockIdx.x, h = blockIdx.y, b = blockIdx.z;
    __shared__ __align__(16) __half sCh[64 * 64];
    __shared__ __align__(16) __half sBh[64 * 64];
    __shared__ __align__(16) __half sBT[64 * 64];
    __shared__ __align__(16) __half sXT[64 * 64];
    __shared__ __align__(16) __half sXwT[64 * 64];
    __shared__ __align__(16) __half sMh[64 * 64];
    __shared__ float slp[64], sdt[64], swf[64];

    int tid = threadIdx.x;
    int l0 = c * 64;
    size_t rowb = (size_t)b * LL;
    const __half* z0 = g_zxh + rowb * (size_t)DIPc;

    uint32_t baseC  = smem_u32(sCh);
    uint32_t baseB  = smem_u32(sBh);
    uint32_t baseBT = smem_u32(sBT);
    uint32_t baseXT = smem_u32(sXT);
    uint32_t baseXw = smem_u32(sXwT);
    uint32_t baseM  = smem_u32(sMh);

    // ---- cp.async staging for C / B / B^T tiles ----
    {
        int crow = tid >> 2;
        int cc0  = (tid & 3) * 2;
        const __half* srcC = g_Cc + ((rowb + l0 + crow) << 6);
        const __half* srcB = g_Bc + ((rowb + l0 + crow) << 6);
        const __half* srcT = g_BT + ((size_t)(b * NE + crow) * LL + l0);
        cp16(baseC  + swzchunk(crow, cc0),     srcC + cc0 * 8);
        cp16(baseC  + swzchunk(crow, cc0 + 1), srcC + cc0 * 8 + 8);
        cp16(baseB  + swzchunk(crow, cc0),     srcB + cc0 * 8);
        cp16(baseB  + swzchunk(crow, cc0 + 1), srcB + cc0 * 8 + 8);
        cp16(baseBT + swzchunk(crow, cc0),     srcT + cc0 * 8);
        cp16(baseBT + swzchunk(crow, cc0 + 1), srcT + cc0 * 8 + 8);
        CP_COMMIT();
    }

    // ---- dt phase: softplus (64 thr) + single-warp shuffle cumsum ----
    float aexp = __expf(A_log[h]);
    if (tid < 64) {
        float raw = g_dtf[(rowb + l0 + tid) * HHc + h] + dt_bias[h];
        float dtv = (raw > 20.f) ? raw : log1pf(__expf(raw));
        sdt[tid] = dtv;
    }
    __syncthreads();
    if (tid < 32) {
        float v0 = sdt[2 * tid], v1 = sdt[2 * tid + 1];
        float ps = v0 + v1;
#pragma unroll
        for (int off = 1; off < 32; off <<= 1) {
            float nv = __shfl_up_sync(0xffffffffu, ps, off);
            if (tid >= off) ps += nv;
        }
        float total = __shfl_sync(0xffffffffu, ps, 31);
        float lp1 = -aexp * ps;
        float lp0 = -aexp * (ps - v1);
        float lpe = -aexp * total;
        slp[2 * tid]     = lp0;
        slp[2 * tid + 1] = lp1;
        swf[2 * tid]     = v0 * __expf(lpe - lp0);
        swf[2 * tid + 1] = v1 * __expf(lpe - lp1);
        size_t lpb = ((size_t)(b * HHc + h) * NCHUNK + c) << 6;
        g_LP[lpb + 2 * tid]     = lp0;
        g_LP[lpb + 2 * tid + 1] = lp1;
    }
    __syncthreads();

    // ---- X conv staging -> sXT, sXwT ----
    {
        int j = tid & 63, tseg = tid >> 6;
        int cxch = h * PP + j;
        float wx0 = cw[cxch*4], wx1 = cw[cxch*4+1], wx2 = cw[cxch*4+2], wx3 = cw[cxch*4+3];
        float bxv = cb[cxch];
        const __half* pxg = z0 + DIc + cxch;
        int t0s = tseg * 16;
        int lbase = l0 + t0s;
        float x0 = 0.f, x1 = 0.f, x2 = 0.f;
        if (lbase - 3 >= 0) x0 = __half2float(pxg[(size_t)(lbase - 3) * DIPc]);
        if (lbase - 2 >= 0) x1 = __half2float(pxg[(size_t)(lbase - 2) * DIPc]);
        if (lbase - 1 >= 0) x2 = __half2float(pxg[(size_t)(lbase - 1) * DIPc]);
#pragma unroll
        for (int it = 0; it < 16; it++) {
            int t = t0s + it;
            float x3 = __half2float(pxg[(size_t)(lbase + it) * DIPc]);
            float ax = bxv + wx0*x0 + wx1*x1 + wx2*x2 + wx3*x3;
            float xs = fsilu(ax);
            *(__half*)((char*)sXT  + swzoff(j, t)) = __float2half(xs);
            *(__half*)((char*)sXwT + swzoff(j, t)) = __float2half(xs * swf[t]);
            x0 = x1; x1 = x2; x2 = x3;
        }
    }
    CP_WAIT0();
    __syncthreads();

    // ---- warp/lane tiling ----
    int warp = tid >> 5, lane = tid & 31;
    int wm = (warp & 1) * 32, wn = (warp >> 1) * 16;
    int g = lane >> 2, tg = lane & 3;
    int arow = wm + (lane & 15);
    int ak = lane >> 4;
    int brow = wn + ((lane >> 4) << 3) + (lane & 7);
    int bk = (lane >> 3) & 1;

    // ---- GEMM1: M = C B^T ----
    float acc1[2][2][4];
#pragma unroll
    for (int i = 0; i < 2; i++)
#pragma unroll
        for (int jn = 0; jn < 2; jn++)
#pragma unroll
            for (int k = 0; k < 4; k++) acc1[i][jn][k] = 0.f;
#pragma unroll
    for (int ks = 0; ks < 4; ks++) {
        uint32_t a0[4], a1[4], bf[4];
        ldsm4(a0, baseC + swzchunk(arow,      ks * 2 + ak));
        ldsm4(a1, baseC + swzchunk(arow + 16, ks * 2 + ak));
        ldsm4(bf, baseB + swzchunk(brow,      ks * 2 + bk));
        mma_f16(acc1[0][0], a0, bf[0], bf[1]);
        mma_f16(acc1[0][1], a0, bf[2], bf[3]);
        mma_f16(acc1[1][0], a1, bf[0], bf[1]);
        mma_f16(acc1[1][1], a1, bf[2], bf[3]);
    }
    // mask (causal, decay, dt) + D_skip on diagonal, store M as fp16
    float ds = D_skip[h];
#pragma unroll
    for (int mt = 0; mt < 2; mt++) {
#pragma unroll
        for (int nt = 0; nt < 2; nt++) {
            int t0 = wm + mt * 16 + g;
            int s0 = wn + nt * 8 + tg * 2;
            float lt0 = slp[t0], lt1 = slp[t0 + 8];
            float ls0 = slp[s0], ls1 = slp[s0 + 1];
            float d0 = sdt[s0], d1 = sdt[s0 + 1];
            float m00 = (s0     <= t0    ) ? acc1[mt][nt][0] * __expf(lt0 - ls0) * d0 : 0.f;
            float m01 = (s0 + 1 <= t0    ) ? acc1[mt][nt][1] * __expf(lt0 - ls1) * d1 : 0.f;
            float m10 = (s0     <= t0 + 8) ? acc1[mt][nt][2] * __expf(lt1 - ls0) * d0 : 0.f;
            float m11 = (s0 + 1 <= t0 + 8) ? acc1[mt][nt][3] * __expf(lt1 - ls1) * d1 : 0.f;
            if (s0     == t0    ) m00 += ds;
            if (s0 + 1 == t0    ) m01 += ds;
            if (s0     == t0 + 8) m10 += ds;
            if (s0 + 1 == t0 + 8) m11 += ds;
            *(__half2*)((char*)sMh + swzoff(t0,     s0)) = __floats2half2_rn(m00, m01);
            *(__half2*)((char*)sMh + swzoff(t0 + 8, s0)) = __floats2half2_rn(m10, m11);
        }
    }
    __syncthreads();

    // ---- GEMM2: Y = M @ X (incl. D*x via diag) ; GEMM3: S = B^T @ (w*X) ----
    float accY[2][2][4], accS[2][2][4];
#pragma unroll
    for (int i = 0; i < 2; i++)
#pragma unroll
        for (int jn = 0; jn < 2; jn++)
#pragma unroll
            for (int k = 0; k < 4; k++) { accY[i][jn][k] = 0.f; accS[i][jn][k] = 0.f; }
#pragma unroll
    for (int ks = 0; ks < 4; ks++) {
        uint32_t am0[4], am1[4], an0[4], an1[4], bfX[4], bfW[4];
        ldsm4(am0, baseM  + swzchunk(arow,      ks * 2 + ak));
        ldsm4(am1, baseM  + swzchunk(arow + 16, ks * 2 + ak));
        ldsm4(an0, baseBT + swzchunk(arow,      ks * 2 + ak));
        ldsm4(an1, baseBT + swzchunk(arow + 16, ks * 2 + ak));
        ldsm4(bfX, baseXT + swzchunk(brow,      ks * 2 + bk));
        ldsm4(bfW, baseXw + swzchunk(brow,      ks * 2 + bk));
        mma_f16(accY[0][0], am0, bfX[0], bfX[1]);
        mma_f16(accY[0][1], am0, bfX[2], bfX[3]);
        mma_f16(accY[1][0], am1, bfX[0], bfX[1]);
        mma_f16(accY[1][1], am1, bfX[2], bfX[3]);
        mma_f16(accS[0][0], an0, bfW[0], bfW[1]);
        mma_f16(accS[0][1], an0, bfW[2], bfW[3]);
        mma_f16(accS[1][0], an1, bfW[0], bfW[1]);
        mma_f16(accS[1][1], an1, bfW[2], bfW[3]);
    }

    // ---- epilogues ----
    size_t sb = ((size_t)(b * HHc + h) * NCHUNK + c) << 12;
#pragma unroll
    for (int mt = 0; mt < 2; mt++) {
#pragma unroll
        for (int nt = 0; nt < 2; nt++) {
            int r0 = wm + mt * 16 + g;
            int c0 = wn + nt * 8 + tg * 2;
            __half* y0 = &g_y[(rowb + l0 + r0) * (size_t)DIc + h * PP + c0];
            __half* y1 = &g_y[(rowb + l0 + r0 + 8) * (size_t)DIc + h * PP + c0];
            *(__half2*)y0 = __floats2half2_rn(accY[mt][nt][0], accY[mt][nt][1]);
            *(__half2*)y1 = __floats2half2_rn(accY[mt][nt][2], accY[mt][nt][3]);
            *(__half2*)&g_Sh[sb + r0 * 64 + c0] =
                __floats2half2_rn(accS[mt][nt][0], accS[mt][nt][1]);
            *(__half2*)&g_Sh[sb + (r0 + 8) * 64 + c0] =
                __floats2half2_rn(accS[mt][nt][2], accS[mt][nt][3]);
        }
    }
}

// state_A: per (b,h) serial H recurrence; snapshots H_entering(c) transposed
// [p][n] fp16 in place into g_Sh slot c (S_c already consumed from smem).
__global__ void __launch_bounds__(256) stateA_kernel() {
    int bh = blockIdx.x;
    __shared__ float sH[64 * 68];                      // H[n][p] fp32
    __shared__ __align__(16) __half sS[2][64 * 72];    // S prefetch
    int tid = threadIdx.x;
    int j = tid & 63, r0 = tid >> 6;
    uint32_t bS[2] = { smem_u32(sS[0]), smem_u32(sS[1]) };

#pragma unroll
    for (int it = 0; it < 16; it++)
        sH[(r0 + it * 4) * 68 + j] = 0.f;

    int pr = tid >> 2, pc = (tid & 3) * 2;
#define SA_PRE(cc, buf) do { \
        const __half* srcS = g_Sh + ((((size_t)bh * NCHUNK + (cc)) << 12) + pr * 64); \
        cp16(bS[buf] + (uint32_t)(pr * 144 + pc * 16),      srcS + pc * 8); \
        cp16(bS[buf] + (uint32_t)(pr * 144 + pc * 16 + 16), srcS + pc * 8 + 8); \
    } while (0)

    SA_PRE(0, 0); CP_COMMIT();

    for (int c = 0; c < NCHUNK; c++) {
        if (c + 1 < NCHUNK) { SA_PRE(c + 1, (c + 1) & 1); CP_COMMIT(); CP_WAIT1(); }
        else CP_WAIT0();
        __syncthreads();   // S_c staged; prev iteration's H update done

        const __half* St = sS[c & 1];
        float P = __expf(g_LP[(((size_t)bh * NCHUNK + c) << 6) + 63]);

        if (c > 0) {
            // snapshot H_entering(c) transposed [p][n] into g_Sh slot c
            __half* dst = g_Sh + (((size_t)bh * NCHUNK + c) << 12);
#pragma unroll
            for (int it = 0; it < 16; it++) {
                int p = r0 + it * 4;
                dst[p * 64 + j] = __float2half(sH[j * 68 + p]);
            }
        }
        __syncthreads();   // snapshot reads done before H update writes

#pragma unroll
        for (int it = 0; it < 16; it++) {
            int n = r0 + it * 4;
            sH[n * 68 + j] = P * sH[n * 68 + j] + __half2float(St[n * 72 + j]);
        }
    }
#undef SA_PRE
}

// state_B: fully parallel correction y += e_t * (C_c @ H_enter^T), tensor-core.
__global__ void __launch_bounds__(256) stateB_kernel() {
    int c = blockIdx.x, h = blockIdx.y, b = blockIdx.z;
    if (c == 0) return;
    __shared__ __align__(16) __half sCh[64 * 64];   // C [t][n] swizzled
    __shared__ __align__(16) __half sHT[64 * 64];   // H^T [p][n] swizzled
    __shared__ float set_[64];

    int tid = threadIdx.x;
    int bh = b * HHc + h;
    size_t rowb = (size_t)b * LL;
    int l0 = c * 64;
    uint32_t baseC = smem_u32(sCh);
    uint32_t baseH = smem_u32(sHT);

    {
        int crow = tid >> 2;
        int cc0  = (tid & 3) * 2;
        const __half* srcC = g_Cc + ((rowb + l0 + crow) << 6);
        const __half* srcH = g_Sh + ((((size_t)bh * NCHUNK + c) << 12) + crow * 64);
        cp16(baseC + swzchunk(crow, cc0),     srcC + cc0 * 8);
        cp16(baseC + swzchunk(crow, cc0 + 1), srcC + cc0 * 8 + 8);
        cp16(baseH + swzchunk(crow, cc0),     srcH + cc0 * 8);
        cp16(baseH + swzchunk(crow, cc0 + 1), srcH + cc0 * 8 + 8);
        CP_COMMIT();
    }
    if (tid < 64)
        set_[tid] = __expf(g_LP[(((size_t)bh * NCHUNK + c) << 6) + tid]);
    CP_WAIT0();
    __syncthreads();

    int warp = tid >> 5, lane = tid & 31;
    int wm = (warp & 1) * 32, wn = (warp >> 1) * 16;
    int g = lane >> 2, tg = lane & 3;
    int arow = wm + (lane & 15);
    int ak = lane >> 4;
    int brow = wn + ((lane >> 4) << 3) + (lane & 7);
    int bk = (lane >> 3) & 1;

    float acc[2][2][4];
#pragma unroll
    for (int i = 0; i < 2; i++)
#pragma unroll
        for (int jn = 0; jn < 2; jn++)
#pragma unroll
            for (int k = 0; k < 4; k++) acc[i][jn][k] = 0.f;
#pragma unroll
    for (int ks = 0; ks < 4; ks++) {
        uint32_t a0[4], a1[4], bf[4];
        ldsm4(a0, baseC + swzchunk(arow,      ks * 2 + ak));
        ldsm4(a1, baseC + swzchunk(arow + 16, ks * 2 + ak));
        ldsm4(bf, baseH + swzchunk(brow,      ks * 2 + bk));
        mma_f16(acc[0][0], a0, bf[0], bf[1]);
        mma_f16(acc[0][1], a0, bf[2], bf[3]);
        mma_f16(acc[1][0], a1, bf[0], bf[1]);
        mma_f16(acc[1][1], a1, bf[2], bf[3]);
    }

#pragma unroll
    for (int mt = 0; mt < 2; mt++) {
#pragma unroll
        for (int nt = 0; nt < 2; nt++) {
            int t0 = wm + mt * 16 + g;
            int p0 = wn + nt * 8 + tg * 2;
            float e0 = set_[t0], e1 = set_[t0 + 8];
            __half* y0 = &g_y[(rowb + l0 + t0) * (size_t)DIc + h * PP + p0];
            __half* y1 = &g_y[(rowb + l0 + t0 + 8) * (size_t)DIc + h * PP + p0];
            float2 f0 = __half22float2(*(__half2*)y0);
            float2 f1 = __half22float2(*(__half2*)y1);
            f0.x += e0 * acc[mt][nt][0]; f0.y += e0 * acc[mt][nt][1];
            f1.x += e1 * acc[mt][nt][2]; f1.y += e1 * acc[mt][nt][3];
            *(__half2*)y0 = __floats2half2_rn(f0.x, f0.y);
            *(__half2*)y1 = __floats2half2_rn(f1.x, f1.y);
        }
    }
}

// ---------------- gate + RMSNorm (vectorized half2) ----------------
__global__ void gate_kernel(const float* __restrict__ norm_w) {
    int row = blockIdx.x;
    int tid = threadIdx.x;
    const __half2* z = (const __half2*)(g_zxh + (size_t)row * DIPc);
    const __half2* y = (const __half2*)(g_y + (size_t)row * DIc);
    __half2* o = (__half2*)(g_gh + (size_t)row * DIc);
    float2 t[3];
    float s2 = 0.f;
#pragma unroll
    for (int r = 0; r < 3; r++) {
        int i = tid + r * 256;
        float2 zz = __half22float2(z[i]);
        float2 yy = __half22float2(y[i]);
        float v0 = yy.x * fsilu(zz.x);
        float v1 = yy.y * fsilu(zz.y);
        t[r] = make_float2(v0, v1);
        s2 += v0 * v0 + v1 * v1;
    }
    __shared__ float red[8];
    for (int o2 = 16; o2; o2 >>= 1) s2 += __shfl_xor_sync(0xffffffffu, s2, o2);
    int warp = tid >> 5, lane = tid & 31;
    if (lane == 0) red[warp] = s2;
    __syncthreads();
    if (warp == 0) {
        s2 = (lane < 8) ? red[lane] : 0.f;
        for (int o2 = 4; o2; o2 >>= 1) s2 += __shfl_xor_sync(0xffffffffu, s2, o2);
        if (lane == 0) red[0] = s2;
    }
    __syncthreads();
    float scale = rsqrtf(red[0] * (1.f / DIc) + 1e-5f);
#pragma unroll
    for (int r = 0; r < 3; r++) {
        int i = tid + r * 256;
        float2 nw = *(const float2*)(norm_w + i * 2);
        o[i] = __floats2half2_rn(t[r].x * scale * nw.x, t[r].y * scale * nw.y);
    }
}

// ---------------- launch ----------------
extern "C" void kernel_launch(void* const* d_in, const int* in_sizes, int n_in,
                              void* d_out, int out_size) {
    const float* x       = (const float*)d_in[0];
    const float* ln_w    = (const float*)d_in[1];
    const float* ln_b    = (const float*)d_in[2];
    const float* Win     = (const float*)d_in[3];
    const float* conv_w  = (const float*)d_in[4];
    const float* conv_b  = (const float*)d_in[5];
    const float* dt_bias = (const float*)d_in[6];
    const float* A_log   = (const float*)d_in[7];
    const float* D_skip  = (const float*)d_in[8];
    const float* norm_w  = (const float*)d_in[9];
    const float* Wout    = (const float*)d_in[10];
    float* out = (float*)d_out;

    __half* zxh_ptr = nullptr; cudaGetSymbolAddress((void**)&zxh_ptr, g_zxh);
    __half* xnh_ptr = nullptr; cudaGetSymbolAddress((void**)&xnh_ptr, g_xnh);
    __half* gh_ptr  = nullptr; cudaGetSymbolAddress((void**)&gh_ptr,  g_gh);
    __half* w1h_ptr = nullptr; cudaGetSymbolAddress((void**)&w1h_ptr, g_w1h);
    __half* w2h_ptr = nullptr; cudaGetSymbolAddress((void**)&w2h_ptr, g_w2h);

    cudaFuncSetAttribute((const void*)gemm_h<DD,  false, true,  true>,
                         cudaFuncAttributeMaxDynamicSharedMemorySize, GSMEM);
    cudaFuncSetAttribute((const void*)gemm_h<DIc, true,  false, false>,
                         cudaFuncAttributeMaxDynamicSharedMemorySize, GSMEM);

    // 1. LayerNorm
    ln_kernel<<<MROWS, 256>>>(x, ln_w, ln_b);
    // 2-3. weight converts
    cvtW1_kernel<<<(NPAD1 * DD + 255) / 256, 256>>>(Win);
    cvtW2_kernel<<<(DD * DIc + 255) / 256, 256>>>(Wout);
    // 4. GEMM1: zxbcdt = xn @ Win^T (fp16 out + fp32 dt capture)  <- profiled
    gemm_h<DD, false, true, true><<<dim3(NPAD1 / 128, MROWS / 128), 256, GSMEM>>>(
        xnh_ptr, w1h_ptr, nullptr, zxh_ptr, DIPc);
    // 5. pre: B/C conv+silu once
    pre_kernel<<<MROWS / 64, 256>>>(conv_w, conv_b);
    // 6. chunked scan part 1
    chunk_kernel<<<dim3(NCHUNK, HHc, BB), 256>>>(
        D_skip, dt_bias, A_log, conv_w, conv_b);
    // 7. state A: serial H recurrence + in-place H snapshots
    stateA_kernel<<<BB * HHc, 256>>>();
    // 8. state B: parallel tensor-core correction
    stateB_kernel<<<dim3(NCHUNK, HHc, BB), 256>>>();
    // 9. gate + RMSNorm
    gate_kernel<<<MROWS, 256>>>(norm_w);
    // 10. GEMM2: out = g @ Wout^T + x
    gemm_h<DIc, true, false, false><<<dim3(DD / 128, MROWS / 128), 256, GSMEM>>>(
        gh_ptr, w2h_ptr, x, out, DD);
}

// round 16
// speedup vs baseline: 1.0862x; 1.0862x over previous
#include <cuda_runtime.h>
#include <cuda_fp16.h>
#include <cstdint>

// Problem constants
#define BB   8
#define LL   4096
#define DD   768
#define NE   64
#define KC   4
#define PP   64
#define DIc  1536
#define HHc  24
#define CDc  1664
#define DIPc 3224
#define MROWS (BB*LL)   // 32768
#define NPAD1 3328
#define NCHUNK 64
#define DTOFF 3200      // = DIc + CDc

// ---------------- workspace ----------------
__device__ __half g_xnh[(size_t)MROWS*DD];
__device__ __half g_zxh[(size_t)MROWS*DIPc];          // GEMM1 out (fp16)
__device__ float  g_dtf[(size_t)MROWS*HHc];           // raw dt columns (fp32)
__device__ __half g_y[(size_t)MROWS*DIc];             // scan out (fp16)
__device__ __half g_gh[(size_t)MROWS*DIc];
__device__ __half g_w1h[(size_t)NPAD1*DD];
__device__ __half g_w2h[(size_t)DD*DIc];
__device__ __half g_Sh[(size_t)BB*HHc*NCHUNK*4096];   // chunk states fp16
__device__ __half g_Bc[(size_t)MROWS*NE];             // conv+silu B  [t][n]
__device__ __half g_Cc[(size_t)MROWS*NE];             // conv+silu C  [t][n]
__device__ __half g_BT[(size_t)BB*NE*LL];             // conv+silu B^T [b][n][t]
__device__ float  g_LP[(size_t)BB*HHc*NCHUNK*64];

// ---------------- helpers ----------------
__device__ __forceinline__ uint32_t smem_u32(const void* p) {
    uint32_t a;
    asm("{ .reg .u64 t; cvta.to.shared.u64 t, %1; cvt.u32.u64 %0, t; }" : "=r"(a) : "l"(p));
    return a;
}
__device__ __forceinline__ void cp16(uint32_t dst, const void* src) {
    asm volatile("cp.async.cg.shared.global [%0], [%1], 16;" :: "r"(dst), "l"(src));
}
#define CP_COMMIT() asm volatile("cp.async.commit_group;" ::: "memory")
#define CP_WAIT1()  asm volatile("cp.async.wait_group 1;" ::: "memory")
#define CP_WAIT0()  asm volatile("cp.async.wait_group 0;" ::: "memory")

__device__ __forceinline__ void ldsm4(uint32_t r[4], uint32_t addr) {
    asm volatile("ldmatrix.sync.aligned.m8n8.x4.shared.b16 {%0,%1,%2,%3}, [%4];"
        : "=r"(r[0]), "=r"(r[1]), "=r"(r[2]), "=r"(r[3]) : "r"(addr));
}

__device__ __forceinline__ void mma_f16(float c[4], const uint32_t a[4],
                                        uint32_t b0, uint32_t b1) {
    asm volatile(
        "mma.sync.aligned.m16n8k16.row.col.f32.f16.f16.f32 "
        "{%0,%1,%2,%3},{%4,%5,%6,%7},{%8,%9},{%0,%1,%2,%3};\n"
        : "+f"(c[0]), "+f"(c[1]), "+f"(c[2]), "+f"(c[3])
        : "r"(a[0]), "r"(a[1]), "r"(a[2]), "r"(a[3]), "r"(b0), "r"(b1));
}

__device__ __forceinline__ float fsilu(float a) {
    return __fdividef(a, 1.f + __expf(-a));
}

// swizzled byte offset within a 64-half (128B) row array
__device__ __forceinline__ int swzoff(int r, int col) {
    return r * 128 + ((((col >> 3) ^ (r & 7)) << 4)) + ((col & 7) << 1);
}
__device__ __forceinline__ uint32_t swzchunk(int r, int chunk) {
    return (uint32_t)(r * 128 + (((chunk ^ (r & 7)) << 4)));
}

// ---------------- fp16 GEMM (templated output type, optional dt capture) -----
static constexpr int GSTAGE = 32768;
static constexpr int GSMEM  = 3 * GSTAGE;

template <int KDIM, bool ADDRES, bool HALFOUT, bool DTW>
__global__ void __launch_bounds__(256, 2) gemm_h(const __half* __restrict__ A,
                                                 const __half* __restrict__ W,
                                                 const float* __restrict__ Res,
                                                 void* __restrict__ OutV, int Ntot) {
    extern __shared__ char smem[];
    uint32_t sbase = smem_u32(smem);
    constexpr int KT = KDIM / 64;

    int tid = threadIdx.x;
    int bm0 = blockIdx.y * 128, bn0 = blockIdx.x * 128;
    int warp = tid >> 5, lane = tid & 31;
    int wm = (warp & 1) * 64, wn = (warp >> 1) * 32;
    int g = lane >> 2, tg = lane & 3;

    float acc[4][4][4];
#pragma unroll
    for (int i = 0; i < 4; i++)
#pragma unroll
        for (int j = 0; j < 4; j++)
#pragma unroll
            for (int k = 0; k < 4; k++) acc[i][j][k] = 0.f;

    int srow = tid >> 1;
    int scb  = (tid & 1) * 4;
    int sswz = srow & 7;
    const __half* gA = A + (size_t)(bm0 + srow) * KDIM + scb * 8;
    const __half* gB = W + (size_t)(bn0 + srow) * KDIM + scb * 8;
    uint32_t stA = sbase + srow * 128;
    uint32_t stB = stA + 16384;

#define LOAD_STAGE(s, t) do { \
        uint32_t so = (uint32_t)(s) * GSTAGE; \
        const __half* a = gA + (t) * 64; \
        const __half* b = gB + (t) * 64; \
        _Pragma("unroll") \
        for (int i = 0; i < 4; i++) { \
            uint32_t off = (uint32_t)(((scb + i) ^ sswz) * 16); \
            cp16(stA + so + off, a + i * 8); \
            cp16(stB + so + off, b + i * 8); \
        } \
    } while (0)

    LOAD_STAGE(0, 0); CP_COMMIT();
    LOAD_STAGE(1, 1); CP_COMMIT();

    int arow = wm + (lane & 15);
    int aks  = lane >> 4;
    int aswz = arow & 7;
    int brow = wn + ((lane >> 4) << 3) + (lane & 7);
    int bks  = (lane >> 3) & 1;
    int bswz = brow & 7;

    for (int t = 0; t < KT; t++) {
        CP_WAIT1();
        __syncthreads();
        if (t + 2 < KT) { LOAD_STAGE((t + 2) % 3, t + 2); CP_COMMIT(); }

        uint32_t Abase = sbase + (uint32_t)(t % 3) * GSTAGE;
        uint32_t Bbase = Abase + 16384;
#pragma unroll
        for (int ks = 0; ks < 4; ks++) {
            uint32_t a[4][4], bb[2][4];
#pragma unroll
            for (int mt = 0; mt < 4; mt++)
                ldsm4(a[mt], Abase + (arow + mt * 16) * 128 +
                              (uint32_t)(((ks * 2 + aks) ^ aswz) * 16));
#pragma unroll
            for (int np = 0; np < 2; np++)
                ldsm4(bb[np], Bbase + (brow + np * 16) * 128 +
                               (uint32_t)(((ks * 2 + bks) ^ bswz) * 16));
#pragma unroll
            for (int mt = 0; mt < 4; mt++)
#pragma unroll
                for (int nt = 0; nt < 4; nt++)
                    mma_f16(acc[mt][nt], a[mt],
                            bb[nt >> 1][(nt & 1) * 2], bb[nt >> 1][(nt & 1) * 2 + 1]);
        }
    }
#undef LOAD_STAGE

#pragma unroll
    for (int mt = 0; mt < 4; mt++) {
        int r0 = bm0 + wm + mt * 16 + g;
#pragma unroll
        for (int nt = 0; nt < 4; nt++) {
            int c0 = bn0 + wn + nt * 8 + tg * 2;
            if (c0 < Ntot) {
                float2 v0 = make_float2(acc[mt][nt][0], acc[mt][nt][1]);
                float2 v1 = make_float2(acc[mt][nt][2], acc[mt][nt][3]);
                if (ADDRES) {
                    float2 x0 = *(const float2*)(Res + (size_t)r0 * Ntot + c0);
                    float2 x1 = *(const float2*)(Res + (size_t)(r0 + 8) * Ntot + c0);
                    v0.x += x0.x; v0.y += x0.y;
                    v1.x += x1.x; v1.y += x1.y;
                }
                if (DTW) {
                    if (c0 >= DTOFF && c0 < DTOFF + HHc) {
                        int dc = c0 - DTOFF;
                        g_dtf[(size_t)r0 * HHc + dc]       = v0.x;
                        g_dtf[(size_t)r0 * HHc + dc + 1]   = v0.y;
                        g_dtf[(size_t)(r0 + 8) * HHc + dc]     = v1.x;
                        g_dtf[(size_t)(r0 + 8) * HHc + dc + 1] = v1.y;
                    }
                }
                if (HALFOUT) {
                    __half* Out = (__half*)OutV;
                    *(__half2*)(Out + (size_t)r0 * Ntot + c0) = __floats2half2_rn(v0.x, v0.y);
                    *(__half2*)(Out + (size_t)(r0 + 8) * Ntot + c0) = __floats2half2_rn(v1.x, v1.y);
                } else {
                    float* Out = (float*)OutV;
                    *(float2*)(Out + (size_t)r0 * Ntot + c0) = v0;
                    *(float2*)(Out + (size_t)(r0 + 8) * Ntot + c0) = v1;
                }
            }
        }
    }
}

// ---------------- LayerNorm (vectorized) + weight convert, block-dispatch ----
__global__ void cvtln_kernel(const float* __restrict__ x,
                             const float* __restrict__ w,
                             const float* __restrict__ b,
                             const float* __restrict__ W1,
                             const float* __restrict__ W2) {
    int blk = blockIdx.x;
    int tid = threadIdx.x;
    if (blk >= MROWS) {
        int idx = (blk - MROWS) * 256 + tid;
        const int N1 = NPAD1 * DD;
        const int N2 = DD * DIc;
        if (idx < N1) {
            int r = idx / DD;
            g_w1h[idx] = (r < DIPc) ? __float2half(W1[idx]) : __half(0.f);
        } else if (idx < N1 + N2) {
            int j = idx - N1;
            g_w2h[j] = __float2half(W2[j]);
        }
        return;
    }
    int row = blk;
    const float* xr = x + (size_t)row * DD;
    float4 v4 = make_float4(0.f, 0.f, 0.f, 0.f);
    float s = 0.f, s2 = 0.f;
    if (tid < 192) {
        v4 = *(const float4*)(xr + tid * 4);
        s  = v4.x + v4.y + v4.z + v4.w;
        s2 = v4.x * v4.x + v4.y * v4.y + v4.z * v4.z + v4.w * v4.w;
    }
    __shared__ float red0[8], red1[8];
    for (int o = 16; o; o >>= 1) {
        s  += __shfl_xor_sync(0xffffffffu, s,  o);
        s2 += __shfl_xor_sync(0xffffffffu, s2, o);
    }
    int warp = tid >> 5, lane = tid & 31;
    if (lane == 0) { red0[warp] = s; red1[warp] = s2; }
    __syncthreads();
    if (warp == 0) {
        s  = (lane < 8) ? red0[lane] : 0.f;
        s2 = (lane < 8) ? red1[lane] : 0.f;
        for (int o = 4; o; o >>= 1) {
            s  += __shfl_xor_sync(0xffffffffu, s,  o);
            s2 += __shfl_xor_sync(0xffffffffu, s2, o);
        }
        if (lane == 0) { red0[0] = s; red1[0] = s2; }
    }
    __syncthreads();
    float mu  = red0[0] * (1.f / DD);
    float var = red1[0] * (1.f / DD) - mu * mu;
    float rs  = rsqrtf(var + 1e-5f);
    if (tid < 192) {
        float4 w4 = *(const float4*)(w + tid * 4);
        float4 b4 = *(const float4*)(b + tid * 4);
        __half2* o = (__half2*)(g_xnh + (size_t)row * DD + tid * 4);
        o[0] = __floats2half2_rn((v4.x - mu) * rs * w4.x + b4.x,
                                 (v4.y - mu) * rs * w4.y + b4.y);
        o[1] = __floats2half2_rn((v4.z - mu) * rs * w4.z + b4.z,
                                 (v4.w - mu) * rs * w4.w + b4.w);
    }
}

// ---------------- pre: conv+silu for B/C channels (h-independent, once) -------
__global__ void __launch_bounds__(256) pre_kernel(const float* __restrict__ cw,
                                                  const float* __restrict__ cb) {
    __shared__ __half sTmp[64][72];
    int blk = blockIdx.x;
    int gl0 = blk * 64;
    int b = gl0 / LL;
    int l0 = gl0 % LL;
    int tid = threadIdx.x;
    int j = tid & 63, seg = tid >> 6;
    const __half* z0 = g_zxh + (size_t)b * LL * DIPc;
    int cBi = DIc + j, cCi = DIc + NE + j;
    float wB0 = cw[cBi*4], wB1 = cw[cBi*4+1], wB2 = cw[cBi*4+2], wB3 = cw[cBi*4+3];
    float wC0 = cw[cCi*4], wC1 = cw[cCi*4+1], wC2 = cw[cCi*4+2], wC3 = cw[cCi*4+3];
    float bBv = cb[cBi], bCv = cb[cCi];
    const __half* pB = z0 + 2 * DIc + j;
    const __half* pC = z0 + 2 * DIc + NE + j;

    int t0 = seg * 16;
    int lb = l0 + t0;
    float B0 = 0.f, B1 = 0.f, B2 = 0.f, C0 = 0.f, C1 = 0.f, C2 = 0.f;
    if (lb - 3 >= 0) { size_t o = (size_t)(lb-3)*DIPc; B0 = __half2float(pB[o]); C0 = __half2float(pC[o]); }
    if (lb - 2 >= 0) { size_t o = (size_t)(lb-2)*DIPc; B1 = __half2float(pB[o]); C1 = __half2float(pC[o]); }
    if (lb - 1 >= 0) { size_t o = (size_t)(lb-1)*DIPc; B2 = __half2float(pB[o]); C2 = __half2float(pC[o]); }
#pragma unroll
    for (int it = 0; it < 16; it++) {
        int t = t0 + it;
        size_t o = (size_t)(lb + it) * DIPc;
        float B3 = __half2float(pB[o]), C3 = __half2float(pC[o]);
        float aB = bBv + wB0*B0 + wB1*B1 + wB2*B2 + wB3*B3;
        float aC = bCv + wC0*C0 + wC1*C1 + wC2*C2 + wC3*C3;
        float Bs = fsilu(aB);
        float Cs = fsilu(aC);
        __half Bh = __float2half(Bs);
        g_Bc[((size_t)(gl0 + t) << 6) + j] = Bh;
        g_Cc[((size_t)(gl0 + t) << 6) + j] = __float2half(Cs);
        sTmp[t][j] = Bh;
        B0 = B1; B1 = B2; B2 = B3;
        C0 = C1; C1 = C2; C2 = C3;
    }
    __syncthreads();
    int n = tid >> 2, tq = tid & 3;
    __half* dst = g_BT + ((size_t)(b * NE + n) * LL + l0 + tq * 16);
#pragma unroll
    for (int i = 0; i < 8; i++) {
        int t = tq * 16 + i * 2;
        *(__half2*)(dst + i * 2) = __halves2half2(sTmp[t][n], sTmp[t + 1][n]);
    }
}

// ================= chunked SSD scan, tensor-core + cp.async staging ==========
__global__ void __launch_bounds__(256, 4) chunk_kernel(const float* __restrict__ D_skip,
                                                       const float* __restrict__ dt_bias,
                                                       const float* __restrict__ A_log,
                                                       const float* __restrict__ cw,
                                                       const float* __restrict__ cb) {
    int c = blockIdx.x, h = blockIdx.y, b = blockIdx.z;
    __shared__ __align__(16) __half sCh[64 * 64];
    __shared__ __align__(16) __half sBh[64 * 64];
    __shared__ __align__(16) __half sBT[64 * 64];
    __shared__ __align__(16) __half sXT[64 * 64];
    __shared__ __align__(16) __half sXwT[64 * 64];
    __shared__ __align__(16) __half sMh[64 * 64];
    __shared__ float slp[64], sdt[64], swf[64];

    int tid = threadIdx.x;
    int l0 = c * 64;
    size_t rowb = (size_t)b * LL;
    const __half* z0 = g_zxh + rowb * (size_t)DIPc;

    uint32_t baseC  = smem_u32(sCh);
    uint32_t baseB  = smem_u32(sBh);
    uint32_t baseBT = smem_u32(sBT);
    uint32_t baseXT = smem_u32(sXT);
    uint32_t baseXw = smem_u32(sXwT);
    uint32_t baseM  = smem_u32(sMh);

    {
        int crow = tid >> 2;
        int cc0  = (tid & 3) * 2;
        const __half* srcC = g_Cc + ((rowb + l0 + crow) << 6);
        const __half* srcB = g_Bc + ((rowb + l0 + crow) << 6);
        const __half* srcT = g_BT + ((size_t)(b * NE + crow) * LL + l0);
        cp16(baseC  + swzchunk(crow, cc0),     srcC + cc0 * 8);
        cp16(baseC  + swzchunk(crow, cc0 + 1), srcC + cc0 * 8 + 8);
        cp16(baseB  + swzchunk(crow, cc0),     srcB + cc0 * 8);
        cp16(baseB  + swzchunk(crow, cc0 + 1), srcB + cc0 * 8 + 8);
        cp16(baseBT + swzchunk(crow, cc0),     srcT + cc0 * 8);
        cp16(baseBT + swzchunk(crow, cc0 + 1), srcT + cc0 * 8 + 8);
        CP_COMMIT();
    }

    float aexp = __expf(A_log[h]);
    if (tid < 64) {
        float raw = g_dtf[(rowb + l0 + tid) * HHc + h] + dt_bias[h];
        float dtv = (raw > 20.f) ? raw : log1pf(__expf(raw));
        sdt[tid] = dtv;
    }
    __syncthreads();
    if (tid < 32) {
        float v0 = sdt[2 * tid], v1 = sdt[2 * tid + 1];
        float ps = v0 + v1;
#pragma unroll
        for (int off = 1; off < 32; off <<= 1) {
            float nv = __shfl_up_sync(0xffffffffu, ps, off);
            if (tid >= off) ps += nv;
        }
        float total = __shfl_sync(0xffffffffu, ps, 31);
        float lp1 = -aexp * ps;
        float lp0 = -aexp * (ps - v1);
        float lpe = -aexp * total;
        slp[2 * tid]     = lp0;
        slp[2 * tid + 1] = lp1;
        swf[2 * tid]     = v0 * __expf(lpe - lp0);
        swf[2 * tid + 1] = v1 * __expf(lpe - lp1);
        size_t lpb = ((size_t)(b * HHc + h) * NCHUNK + c) << 6;
        g_LP[lpb + 2 * tid]     = lp0;
        g_LP[lpb + 2 * tid + 1] = lp1;
    }
    __syncthreads();

    {
        int j = tid & 63, tseg = tid >> 6;
        int cxch = h * PP + j;
        float wx0 = cw[cxch*4], wx1 = cw[cxch*4+1], wx2 = cw[cxch*4+2], wx3 = cw[cxch*4+3];
        float bxv = cb[cxch];
        const __half* pxg = z0 + DIc + cxch;
        int t0s = tseg * 16;
        int lbase = l0 + t0s;
        float x0 = 0.f, x1 = 0.f, x2 = 0.f;
        if (lbase - 3 >= 0) x0 = __half2float(pxg[(size_t)(lbase - 3) * DIPc]);
        if (lbase - 2 >= 0) x1 = __half2float(pxg[(size_t)(lbase - 2) * DIPc]);
        if (lbase - 1 >= 0) x2 = __half2float(pxg[(size_t)(lbase - 1) * DIPc]);
#pragma unroll
        for (int it = 0; it < 16; it++) {
            int t = t0s + it;
            float x3 = __half2float(pxg[(size_t)(lbase + it) * DIPc]);
            float ax = bxv + wx0*x0 + wx1*x1 + wx2*x2 + wx3*x3;
            float xs = fsilu(ax);
            *(__half*)((char*)sXT  + swzoff(j, t)) = __float2half(xs);
            *(__half*)((char*)sXwT + swzoff(j, t)) = __float2half(xs * swf[t]);
            x0 = x1; x1 = x2; x2 = x3;
        }
    }
    CP_WAIT0();
    __syncthreads();

    int warp = tid >> 5, lane = tid & 31;
    int wm = (warp & 1) * 32, wn = (warp >> 1) * 16;
    int g = lane >> 2, tg = lane & 3;
    int arow = wm + (lane & 15);
    int ak = lane >> 4;
    int brow = wn + ((lane >> 4) << 3) + (lane & 7);
    int bk = (lane >> 3) & 1;

    float acc1[2][2][4];
#pragma unroll
    for (int i = 0; i < 2; i++)
#pragma unroll
        for (int jn = 0; jn < 2; jn++)
#pragma unroll
            for (int k = 0; k < 4; k++) acc1[i][jn][k] = 0.f;
#pragma unroll
    for (int ks = 0; ks < 4; ks++) {
        uint32_t a0[4], a1[4], bf[4];
        ldsm4(a0, baseC + swzchunk(arow,      ks * 2 + ak));
        ldsm4(a1, baseC + swzchunk(arow + 16, ks * 2 + ak));
        ldsm4(bf, baseB + swzchunk(brow,      ks * 2 + bk));
        mma_f16(acc1[0][0], a0, bf[0], bf[1]);
        mma_f16(acc1[0][1], a0, bf[2], bf[3]);
        mma_f16(acc1[1][0], a1, bf[0], bf[1]);
        mma_f16(acc1[1][1], a1, bf[2], bf[3]);
    }
    float ds = D_skip[h];
#pragma unroll
    for (int mt = 0; mt < 2; mt++) {
#pragma unroll
        for (int nt = 0; nt < 2; nt++) {
            int t0 = wm + mt * 16 + g;
            int s0 = wn + nt * 8 + tg * 2;
            float lt0 = slp[t0], lt1 = slp[t0 + 8];
            float ls0 = slp[s0], ls1 = slp[s0 + 1];
            float d0 = sdt[s0], d1 = sdt[s0 + 1];
            float m00 = (s0     <= t0    ) ? acc1[mt][nt][0] * __expf(lt0 - ls0) * d0 : 0.f;
            float m01 = (s0 + 1 <= t0    ) ? acc1[mt][nt][1] * __expf(lt0 - ls1) * d1 : 0.f;
            float m10 = (s0     <= t0 + 8) ? acc1[mt][nt][2] * __expf(lt1 - ls0) * d0 : 0.f;
            float m11 = (s0 + 1 <= t0 + 8) ? acc1[mt][nt][3] * __expf(lt1 - ls1) * d1 : 0.f;
            if (s0     == t0    ) m00 += ds;
            if (s0 + 1 == t0    ) m01 += ds;
            if (s0     == t0 + 8) m10 += ds;
            if (s0 + 1 == t0 + 8) m11 += ds;
            *(__half2*)((char*)sMh + swzoff(t0,     s0)) = __floats2half2_rn(m00, m01);
            *(__half2*)((char*)sMh + swzoff(t0 + 8, s0)) = __floats2half2_rn(m10, m11);
        }
    }
    __syncthreads();

    float accY[2][2][4], accS[2][2][4];
#pragma unroll
    for (int i = 0; i < 2; i++)
#pragma unroll
        for (int jn = 0; jn < 2; jn++)
#pragma unroll
            for (int k = 0; k < 4; k++) { accY[i][jn][k] = 0.f; accS[i][jn][k] = 0.f; }
#pragma unroll
    for (int ks = 0; ks < 4; ks++) {
        uint32_t am0[4], am1[4], an0[4], an1[4], bfX[4], bfW[4];
        ldsm4(am0, baseM  + swzchunk(arow,      ks * 2 + ak));
        ldsm4(am1, baseM  + swzchunk(arow + 16, ks * 2 + ak));
        ldsm4(an0, baseBT + swzchunk(arow,      ks * 2 + ak));
        ldsm4(an1, baseBT + swzchunk(arow + 16, ks * 2 + ak));
        ldsm4(bfX, baseXT + swzchunk(brow,      ks * 2 + bk));
        ldsm4(bfW, baseXw + swzchunk(brow,      ks * 2 + bk));
        mma_f16(accY[0][0], am0, bfX[0], bfX[1]);
        mma_f16(accY[0][1], am0, bfX[2], bfX[3]);
        mma_f16(accY[1][0], am1, bfX[0], bfX[1]);
        mma_f16(accY[1][1], am1, bfX[2], bfX[3]);
        mma_f16(accS[0][0], an0, bfW[0], bfW[1]);
        mma_f16(accS[0][1], an0, bfW[2], bfW[3]);
        mma_f16(accS[1][0], an1, bfW[0], bfW[1]);
        mma_f16(accS[1][1], an1, bfW[2], bfW[3]);
    }

    size_t sb = ((size_t)(b * HHc + h) * NCHUNK + c) << 12;
#pragma unroll
    for (int mt = 0; mt < 2; mt++) {
#pragma unroll
        for (int nt = 0; nt < 2; nt++) {
            int r0 = wm + mt * 16 + g;
            int c0 = wn + nt * 8 + tg * 2;
            __half* y0 = &g_y[(rowb + l0 + r0) * (size_t)DIc + h * PP + c0];
            __half* y1 = &g_y[(rowb + l0 + r0 + 8) * (size_t)DIc + h * PP + c0];
            *(__half2*)y0 = __floats2half2_rn(accY[mt][nt][0], accY[mt][nt][1]);
            *(__half2*)y1 = __floats2half2_rn(accY[mt][nt][2], accY[mt][nt][3]);
            *(__half2*)&g_Sh[sb + r0 * 64 + c0] =
                __floats2half2_rn(accS[mt][nt][0], accS[mt][nt][1]);
            *(__half2*)&g_Sh[sb + (r0 + 8) * 64 + c0] =
                __floats2half2_rn(accS[mt][nt][2], accS[mt][nt][3]);
        }
    }
}

// CH2: per (b,h): serial chunk recurrence with double-buffered cp.async prefetch
#define SROW 68
__global__ void __launch_bounds__(256) state_kernel() {
    int bh = blockIdx.x;
    int b = bh / HHc, h = bh % HHc;
    __shared__ float sH[64 * SROW];                    // H[n][p] fp32
    __shared__ __align__(16) __half sCb[2][64 * 72];   // raw C [t][n]
    __shared__ __align__(16) __half sSb[2][64 * 72];   // raw S [n][p]
    __shared__ __align__(16) float  sLP[2][64];

    int tid = threadIdx.x;
    int j = tid & 63, r0 = tid >> 6;
    int i = tid & 15, jq = tid >> 4;
    size_t rowb = (size_t)b * LL;

    uint32_t bC[2] = { smem_u32(sCb[0]), smem_u32(sCb[1]) };
    uint32_t bS[2] = { smem_u32(sSb[0]), smem_u32(sSb[1]) };
    uint32_t bL[2] = { smem_u32(sLP[0]), smem_u32(sLP[1]) };

#pragma unroll
    for (int it = 0; it < 16; it++) {
        int n = r0 + it * 4;
        sH[n * SROW + j] = 0.f;
    }

    int pr = tid >> 2;
    int pc = (tid & 3) * 2;

#define ST_PREFETCH(cc, buf) do { \
        const __half* srcC = g_Cc + ((rowb + (cc) * 64 + pr) << 6); \
        const __half* srcS = g_Sh + ((((size_t)bh * NCHUNK + (cc)) << 12) + pr * 64); \
        cp16(bC[buf] + (uint32_t)(pr * 144 + pc * 16),      srcC + pc * 8); \
        cp16(bC[buf] + (uint32_t)(pr * 144 + pc * 16 + 16), srcC + pc * 8 + 8); \
        cp16(bS[buf] + (uint32_t)(pr * 144 + pc * 16),      srcS + pc * 8); \
        cp16(bS[buf] + (uint32_t)(pr * 144 + pc * 16 + 16), srcS + pc * 8 + 8); \
        if (tid < 16) \
            cp16(bL[buf] + tid * 16, \
                 g_LP + ((((size_t)bh * NCHUNK + (cc)) << 6) + tid * 4)); \
    } while (0)

    ST_PREFETCH(0, 0); CP_COMMIT();

    for (int c = 0; c < NCHUNK; c++) {
        if (c + 1 < NCHUNK) { ST_PREFETCH(c + 1, (c + 1) & 1); CP_COMMIT(); CP_WAIT1(); }
        else CP_WAIT0();
        __syncthreads();

        const __half* Ct = sCb[c & 1];
        const __half* St = sSb[c & 1];
        const float*  Lt = sLP[c & 1];
        float P = __expf(Lt[63]);

        if (c > 0) {
            float acc[4][4];
#pragma unroll
            for (int a = 0; a < 4; a++)
#pragma unroll
                for (int d = 0; d < 4; d++) acc[a][d] = 0.f;
            for (int n = 0; n < 64; n += 2) {
                float2 c0 = __half22float2(*(const __half2*)&Ct[i * 72 + n]);
                float2 c1 = __half22float2(*(const __half2*)&Ct[(i + 16) * 72 + n]);
                float2 c2 = __half22float2(*(const __half2*)&Ct[(i + 32) * 72 + n]);
                float2 c3 = __half22float2(*(const __half2*)&Ct[(i + 48) * 72 + n]);
                float4 h4a = *(const float4*)&sH[n * SROW + jq * 4];
                float4 h4b = *(const float4*)&sH[(n + 1) * SROW + jq * 4];
                acc[0][0] += c0.x * h4a.x + c0.y * h4b.x;
                acc[0][1] += c0.x * h4a.y + c0.y * h4b.y;
                acc[0][2] += c0.x * h4a.z + c0.y * h4b.z;
                acc[0][3] += c0.x * h4a.w + c0.y * h4b.w;
                acc[1][0] += c1.x * h4a.x + c1.y * h4b.x;
                acc[1][1] += c1.x * h4a.y + c1.y * h4b.y;
                acc[1][2] += c1.x * h4a.z + c1.y * h4b.z;
                acc[1][3] += c1.x * h4a.w + c1.y * h4b.w;
                acc[2][0] += c2.x * h4a.x + c2.y * h4b.x;
                acc[2][1] += c2.x * h4a.y + c2.y * h4b.y;
                acc[2][2] += c2.x * h4a.z + c2.y * h4b.z;
                acc[2][3] += c2.x * h4a.w + c2.y * h4b.w;
                acc[3][0] += c3.x * h4a.x + c3.y * h4b.x;
                acc[3][1] += c3.x * h4a.y + c3.y * h4b.y;
                acc[3][2] += c3.x * h4a.z + c3.y * h4b.z;
                acc[3][3] += c3.x * h4a.w + c3.y * h4b.w;
            }
#pragma unroll
            for (int a = 0; a < 4; a++) {
                int t = i + 16 * a;
                float e = __expf(Lt[t]);
                __half* yp = &g_y[(rowb + c * 64 + t) * (size_t)DIc + h * PP + jq * 4];
                __half2 y01 = *(__half2*)yp;
                __half2 y23 = *(__half2*)(yp + 2);
                float2 f01 = __half22float2(y01);
                float2 f23 = __half22float2(y23);
                f01.x += e * acc[a][0]; f01.y += e * acc[a][1];
                f23.x += e * acc[a][2]; f23.y += e * acc[a][3];
                *(__half2*)yp       = __floats2half2_rn(f01.x, f01.y);
                *(__half2*)(yp + 2) = __floats2half2_rn(f23.x, f23.y);
            }
        }
        __syncthreads();

#pragma unroll
        for (int it = 0; it < 16; it++) {
            int n = r0 + it * 4;
            sH[n * SROW + j] = P * sH[n * SROW + j] +
                               __half2float(St[n * 72 + j]);
        }
        __syncthreads();
    }
#undef ST_PREFETCH
}

// ---------------- gate + RMSNorm (16B vectorized, 192 active threads) --------
__global__ void gate_kernel(const float* __restrict__ norm_w) {
    int row = blockIdx.x;
    int tid = threadIdx.x;
    const __half2* z = (const __half2*)(g_zxh + (size_t)row * DIPc);
    const __half2* y = (const __half2*)(g_y + (size_t)row * DIc);
    __half2* o = (__half2*)(g_gh + (size_t)row * DIc);

    float v[8];
    float s2 = 0.f;
    if (tid < 192) {
        // one 16B load each of y and z: 4 half2 = 8 values
        uint4 yv = *(const uint4*)(y + tid * 4);
        uint4 zv = *(const uint4*)(z + tid * 4);
        const __half2* yh = (const __half2*)&yv;
        const __half2* zh = (const __half2*)&zv;
#pragma unroll
        for (int q = 0; q < 4; q++) {
            float2 zz = __half22float2(zh[q]);
            float2 yy = __half22float2(yh[q]);
            v[q * 2]     = yy.x * fsilu(zz.x);
            v[q * 2 + 1] = yy.y * fsilu(zz.y);
            s2 += v[q * 2] * v[q * 2] + v[q * 2 + 1] * v[q * 2 + 1];
        }
    }
    __shared__ float red[8];
    for (int o2 = 16; o2; o2 >>= 1) s2 += __shfl_xor_sync(0xffffffffu, s2, o2);
    int warp = tid >> 5, lane = tid & 31;
    if (lane == 0) red[warp] = s2;
    __syncthreads();
    if (warp == 0) {
        s2 = (lane < 8) ? red[lane] : 0.f;
        for (int o2 = 4; o2; o2 >>= 1) s2 += __shfl_xor_sync(0xffffffffu, s2, o2);
        if (lane == 0) red[0] = s2;
    }
    __syncthreads();
    float scale = rsqrtf(red[0] * (1.f / DIc) + 1e-5f);
    if (tid < 192) {
        float4 nw0 = *(const float4*)(norm_w + tid * 8);
        float4 nw1 = *(const float4*)(norm_w + tid * 8 + 4);
        uint4 ov;
        __half2* oh = (__half2*)&ov;
        oh[0] = __floats2half2_rn(v[0] * scale * nw0.x, v[1] * scale * nw0.y);
        oh[1] = __floats2half2_rn(v[2] * scale * nw0.z, v[3] * scale * nw0.w);
        oh[2] = __floats2half2_rn(v[4] * scale * nw1.x, v[5] * scale * nw1.y);
        oh[3] = __floats2half2_rn(v[6] * scale * nw1.z, v[7] * scale * nw1.w);
        *(uint4*)(o + tid * 4) = ov;
    }
}

// ---------------- launch ----------------
extern "C" void kernel_launch(void* const* d_in, const int* in_sizes, int n_in,
                              void* d_out, int out_size) {
    const float* x       = (const float*)d_in[0];
    const float* ln_w    = (const float*)d_in[1];
    const float* ln_b    = (const float*)d_in[2];
    const float* Win     = (const float*)d_in[3];
    const float* conv_w  = (const float*)d_in[4];
    const float* conv_b  = (const float*)d_in[5];
    const float* dt_bias = (const float*)d_in[6];
    const float* A_log   = (const float*)d_in[7];
    const float* D_skip  = (const float*)d_in[8];
    const float* norm_w  = (const float*)d_in[9];
    const float* Wout    = (const float*)d_in[10];
    float* out = (float*)d_out;

    __half* zxh_ptr = nullptr; cudaGetSymbolAddress((void**)&zxh_ptr, g_zxh);
    __half* xnh_ptr = nullptr; cudaGetSymbolAddress((void**)&xnh_ptr, g_xnh);
    __half* gh_ptr  = nullptr; cudaGetSymbolAddress((void**)&gh_ptr,  g_gh);
    __half* w1h_ptr = nullptr; cudaGetSymbolAddress((void**)&w1h_ptr, g_w1h);
    __half* w2h_ptr = nullptr; cudaGetSymbolAddress((void**)&w2h_ptr, g_w2h);

    cudaFuncSetAttribute((const void*)gemm_h<DD,  false, true,  true>,
                         cudaFuncAttributeMaxDynamicSharedMemorySize, GSMEM);
    cudaFuncSetAttribute((const void*)gemm_h<DIc, true,  false, false>,
                         cudaFuncAttributeMaxDynamicSharedMemorySize, GSMEM);

    // 1. LayerNorm + weight convert (merged)
    {
        int cvt_total = NPAD1 * DD + DD * DIc;
        int cvt_blocks = (cvt_total + 255) / 256;
        cvtln_kernel<<<MROWS + cvt_blocks, 256>>>(x, ln_w, ln_b, Win, Wout);
    }
    // 2. GEMM1: zxbcdt = xn @ Win^T (fp16 out + fp32 dt capture)
    gemm_h<DD, false, true, true><<<dim3(NPAD1 / 128, MROWS / 128), 256, GSMEM>>>(
        xnh_ptr, w1h_ptr, nullptr, zxh_ptr, DIPc);
    // 3. pre: B/C conv+silu once
    pre_kernel<<<MROWS / 64, 256>>>(conv_w, conv_b);
    // 4. chunked scan part 1   <- profiled launch
    chunk_kernel<<<dim3(NCHUNK, HHc, BB), 256>>>(
        D_skip, dt_bias, A_log, conv_w, conv_b);
    // 5. chunked scan part 2 (prefetched serial recurrence)
    state_kernel<<<BB * HHc, 256>>>();
    // 6. gate + RMSNorm
    gate_kernel<<<MROWS, 256>>>(norm_w);
    // 7. GEMM2: out = g @ Wout^T + x
    gemm_h<DIc, true, false, false><<<dim3(DD / 128, MROWS / 128), 256, GSMEM>>>(
        gh_ptr, w2h_ptr, x, out, DD);
}